// round 15
// baseline (speedup 1.0000x reference)
#include <cuda_runtime.h>
#include <cuda_fp16.h>
#include <cstdint>

// Problem constants
#define D_IN   1024
#define NSEQ   2048
#define BATCH  4
#define NHEAD  16
#define HDIM   64
#define MTOT   (BATCH*NSEQ)   // 8192
#define GK     1024

// ---------------------------------------------------------------------------
// Scratch (no cudaMalloc allowed)
// ---------------------------------------------------------------------------
__device__ __half g_Xh[(size_t)MTOT * D_IN];
__device__ __half g_Ch[(size_t)MTOT * D_IN];            // ctx hi
__device__ __half g_Wth[(size_t)4 * D_IN * D_IN];       // Wq|Wk|Wv|Wo transposed
__device__ __half g_Qh[(size_t)MTOT * D_IN];
__device__ __half g_Kh[(size_t)MTOT * D_IN];
__device__ __half g_Vth[(size_t)BATCH * NHEAD * HDIM * NSEQ];

__device__ __forceinline__ float fexp2(float x) {
    float r;
    asm("ex2.approx.f32 %0, %1;" : "=f"(r) : "f"(x));
    return r;
}
__device__ __forceinline__ uint32_t smem_u32(const void* p) {
    uint32_t a;
    asm("{ .reg .u64 t; cvta.to.shared.u64 t, %1; cvt.u32.u64 %0, t; }" : "=r"(a) : "l"(p));
    return a;
}
__device__ __forceinline__ void cp16(uint32_t saddr, const void* gptr) {
    asm volatile("cp.async.cg.shared.global [%0], [%1], 16;" :: "r"(saddr), "l"(gptr));
}
__device__ __forceinline__ void ldsm4(uint32_t* r, uint32_t saddr) {
    asm volatile("ldmatrix.sync.aligned.m8n8.x4.shared.b16 {%0,%1,%2,%3}, [%4];"
        : "=r"(r[0]), "=r"(r[1]), "=r"(r[2]), "=r"(r[3]) : "r"(saddr));
}
__device__ __forceinline__ void mma_f16(float* c, const uint32_t* a,
                                        uint32_t b0, uint32_t b1)
{
    asm volatile(
        "mma.sync.aligned.m16n8k16.row.col.f32.f16.f16.f32 "
        "{%0,%1,%2,%3}, {%4,%5,%6,%7}, {%8,%9}, {%0,%1,%2,%3};"
        : "+f"(c[0]), "+f"(c[1]), "+f"(c[2]), "+f"(c[3])
        : "r"(a[0]), "r"(a[1]), "r"(a[2]), "r"(a[3]), "r"(b0), "r"(b1));
}

// ---------------------------------------------------------------------------
// Convert fp32 -> fp16 (X only)
// ---------------------------------------------------------------------------
__global__ __launch_bounds__(256) void conv_kernel(
    const float* __restrict__ x, __half* __restrict__ hi)
{
    size_t i = (size_t)blockIdx.x * 256 + threadIdx.x;
    float4 v = ((const float4*)x)[i];
    __half2 hv0 = __float22half2_rn(make_float2(v.x, v.y));
    __half2 hv1 = __float22half2_rn(make_float2(v.z, v.w));
    ((__half2*)hi)[i * 2 + 0] = hv0;
    ((__half2*)hi)[i * 2 + 1] = hv1;
}

// ---------------------------------------------------------------------------
// Batched transpose: z selects Wq/Wk/Wv/Wo -> Wt[z*1024 + N][K] fp16
// ---------------------------------------------------------------------------
__global__ __launch_bounds__(256) void transpose4_kernel(
    const float* __restrict__ W0, const float* __restrict__ W1,
    const float* __restrict__ W2, const float* __restrict__ W3,
    __half* __restrict__ Th)
{
    __shared__ float t[32][33];
    const int z = blockIdx.z;
    const float* W = (z == 0) ? W0 : (z == 1) ? W1 : (z == 2) ? W2 : W3;
    const int rowOff = z * 1024;
    int x0 = blockIdx.x * 32, y0 = blockIdx.y * 32;
    int tx = threadIdx.x, ty = threadIdx.y;  // (32, 8)
    #pragma unroll
    for (int j = 0; j < 32; j += 8)
        t[ty + j][tx] = W[(size_t)(y0 + ty + j) * D_IN + x0 + tx];
    __syncthreads();
    #pragma unroll
    for (int j = 0; j < 32; j += 8)
        Th[(size_t)(rowOff + x0 + ty + j) * GK + y0 + tx] =
            __float2half_rn(t[tx][ty + j]);
}

// ---------------------------------------------------------------------------
// Pipelined fp16 GEMM (1-MMA), cp.async double-buffered, ldmatrix fragments.
// EPI 0: fp32 + bias.  EPI 1: fused QKV epilogue routing.
// ---------------------------------------------------------------------------
#define BK2 32
#define AS2 40
#define MAT_E (128 * AS2)
#define STG_E (4 * MAT_E)
#define GSMEM (2 * STG_E * 2)      // 81920 bytes
#define VT_STR 136

template<int EPI>
__global__ __launch_bounds__(256, 2) void gemm_ld_kernel(
    const __half* __restrict__ Ah_, const __half* __restrict__ Bh_,
    const float* __restrict__ bias, float* __restrict__ C,
    __half* __restrict__ oQh, __half* __restrict__ oKh,
    __half* __restrict__ oVth)
{
    extern __shared__ __half smem[];
    const int tid = threadIdx.x;
    const int wid = tid >> 5, lane = tid & 31;
    const int g = lane >> 2, tig = lane & 3;
    const int warpRow = (wid >> 1) * 32;
    const int warpCol = (wid & 1) * 64;
    const int rowBase = blockIdx.y * 128;
    const int colBase = blockIdx.x * 128;

    const __half* gA0 = Ah_ + (size_t)rowBase * GK;
    const __half* gB0 = Bh_ + (size_t)colBase * GK;

    float acc[2][8][4];
    #pragma unroll
    for (int mt = 0; mt < 2; mt++)
        #pragma unroll
        for (int nt = 0; nt < 8; nt++)
            #pragma unroll
            for (int j = 0; j < 4; j++) acc[mt][nt][j] = 0.f;

    const int lr = tid >> 1, lh = tid & 1;
    const uint32_t sbase = smem_u32(smem);
    const size_t gbase = (size_t)lr * GK + lh * 16;
    const uint32_t sb0 = sbase + (lr * AS2 + lh * 16) * 2;

    const int frow = (lane & 7) + ((lane >> 3) & 1) * 8;
    const int fcol = (lane >> 4) * 8;

    const int NIT = GK / BK2;  // 32

    {
        #pragma unroll
        for (int c = 0; c < 2; c++) {
            cp16(sb0 + c * 16 + 0 * MAT_E * 2, gA0 + gbase + c * 8);
            cp16(sb0 + c * 16 + 2 * MAT_E * 2, gB0 + gbase + c * 8);
        }
        asm volatile("cp.async.commit_group;" ::: "memory");
    }

    for (int it = 0; it < NIT; it++) {
        if (it + 1 < NIT) {
            const int k0 = (it + 1) * BK2;
            const uint32_t sb = sb0 + ((it + 1) & 1) * STG_E * 2;
            #pragma unroll
            for (int c = 0; c < 2; c++) {
                cp16(sb + c * 16 + 0 * MAT_E * 2, gA0 + gbase + k0 + c * 8);
                cp16(sb + c * 16 + 2 * MAT_E * 2, gB0 + gbase + k0 + c * 8);
            }
            asm volatile("cp.async.commit_group;" ::: "memory");
            asm volatile("cp.async.wait_group 1;" ::: "memory");
        } else {
            asm volatile("cp.async.wait_group 0;" ::: "memory");
        }
        __syncthreads();

        const uint32_t stg = sbase + (it & 1) * STG_E * 2;

        #pragma unroll
        for (int ks = 0; ks < 2; ks++) {
            const uint32_t cb = (uint32_t)(ks * 16 + fcol) * 2;
            uint32_t ah[2][4];
            #pragma unroll
            for (int mt = 0; mt < 2; mt++) {
                const uint32_t rb = (uint32_t)(warpRow + mt * 16 + frow) * (AS2 * 2);
                ldsm4(ah[mt], stg + 0 * MAT_E * 2 + rb + cb);
            }
            #pragma unroll
            for (int ntp = 0; ntp < 4; ntp++) {
                const uint32_t rb = (uint32_t)(warpCol + ntp * 16 + frow) * (AS2 * 2);
                uint32_t bh4[4];
                ldsm4(bh4, stg + 2 * MAT_E * 2 + rb + cb);
                #pragma unroll
                for (int s = 0; s < 2; s++) {
                    const int nt = ntp * 2 + s;
                    #pragma unroll
                    for (int mt = 0; mt < 2; mt++)
                        mma_f16(acc[mt][nt], ah[mt], bh4[s], bh4[2 + s]);
                }
            }
        }
        __syncthreads();
    }

    // ---------------- epilogue ----------------
    if (EPI == 1) {
        const int region = colBase >> 10;   // 0:Q 1:K 2:V
        if (region == 2) {
            __half* tH = smem;   // [128][VT_STR]
            #pragma unroll
            for (int mt = 0; mt < 2; mt++) {
                #pragma unroll
                for (int nt = 0; nt < 8; nt++) {
                    const int cl = warpCol + nt * 8 + tig * 2;
                    const int rl = warpRow + mt * 16 + g;
                    #pragma unroll
                    for (int j = 0; j < 4; j++) {
                        const int c = cl + (j & 1);
                        const int r = rl + (j >> 1) * 8;
                        tH[c * VT_STR + r] = __float2half_rn(acc[mt][nt][j]);
                    }
                }
            }
            __syncthreads();
            const int dl = tid >> 1, hf = tid & 1;
            const int bq = rowBase / NSEQ;
            const int seq0 = rowBase & (NSEQ - 1);
            const int h0 = (colBase & 1023) >> 6;
            const size_t orow =
                ((size_t)(bq * NHEAD + h0) * HDIM + dl) * NSEQ + seq0 + hf * 64;
            const __half* sH = tH + dl * VT_STR + hf * 64;
            #pragma unroll
            for (int u = 0; u < 8; u++)
                *(uint4*)(oVth + orow + u * 8) = *(const uint4*)(sH + u * 8);
            return;
        }
        __half* Ho = (region == 0) ? oQh : oKh;
        #pragma unroll
        for (int mt = 0; mt < 2; mt++) {
            #pragma unroll
            for (int nt = 0; nt < 8; nt++) {
                const int r0 = rowBase + warpRow + mt * 16 + g;
                const int col = (colBase & 1023) + warpCol + nt * 8 + tig * 2;
                __half2 h0 = __float22half2_rn(make_float2(acc[mt][nt][0], acc[mt][nt][1]));
                __half2 h1 = __float22half2_rn(make_float2(acc[mt][nt][2], acc[mt][nt][3]));
                *(uint32_t*)(Ho + (size_t)r0 * D_IN + col) = *(uint32_t*)&h0;
                *(uint32_t*)(Ho + (size_t)(r0 + 8) * D_IN + col) = *(uint32_t*)&h1;
            }
        }
        return;
    }

    #pragma unroll
    for (int mt = 0; mt < 2; mt++) {
        #pragma unroll
        for (int nt = 0; nt < 8; nt++) {
            const int r0 = rowBase + warpRow + mt * 16 + g;
            const int col = colBase + warpCol + nt * 8 + tig * 2;
            float bx = bias[col], by = bias[col + 1];
            float2 v0 = {acc[mt][nt][0] + bx, acc[mt][nt][1] + by};
            float2 v1 = {acc[mt][nt][2] + bx, acc[mt][nt][3] + by};
            *(float2*)(C + (size_t)r0 * D_IN + col) = v0;
            *(float2*)(C + (size_t)(r0 + 8) * D_IN + col) = v1;
        }
    }
}

// ---------------------------------------------------------------------------
// Tensor-core causal flash attention, fp16, ldmatrix fragments, 2 CTAs/SM.
// ---------------------------------------------------------------------------
#define KSTR 72
#define TILE_B2 (64 * KSTR * 2)
#define ASTAGE_B (2 * TILE_B2)
#define ATTN_SMEM2 (2 * ASTAGE_B)        // 36864 bytes
#define EXP_C 0.1803368801111204f        // log2(e)/8

__global__ __launch_bounds__(256, 2) void attn_mma_kernel(
    const __half* __restrict__ Qh, const __half* __restrict__ Kh,
    const __half* __restrict__ Vth, __half* __restrict__ Ch)
{
    extern __shared__ __half asmem[];
    const uint32_t sb = smem_u32(asmem);

    const int tid = threadIdx.x;
    const int wid = tid >> 5, lane = tid & 31;
    const int g = lane >> 2, tig = lane & 3;
    const int q0 = ((int)gridDim.x - 1 - (int)blockIdx.x) * 128;
    const int h = blockIdx.y, b = blockIdx.z;
    const int bh = b * NHEAD + h;
    const int rA = q0 + wid * 16 + g;
    const int rB = rA + 8;

    const int frow = (lane & 7) + ((lane >> 3) & 1) * 8;
    const int fcol = (lane >> 4) * 8;

    const size_t qrow = (size_t)(b * NSEQ + q0 + wid * 16) * D_IN + h * HDIM;
    uint32_t qh[4][4];
    #pragma unroll
    for (int ks = 0; ks < 4; ks++) {
        const int col = ks * 16 + tig * 2;
        qh[ks][0] = *(const uint32_t*)(Qh + qrow + (size_t)g * D_IN + col);
        qh[ks][1] = *(const uint32_t*)(Qh + qrow + (size_t)(g + 8) * D_IN + col);
        qh[ks][2] = *(const uint32_t*)(Qh + qrow + (size_t)g * D_IN + col + 8);
        qh[ks][3] = *(const uint32_t*)(Qh + qrow + (size_t)(g + 8) * D_IN + col + 8);
    }

    float O[8][4];
    #pragma unroll
    for (int nt = 0; nt < 8; nt++)
        #pragma unroll
        for (int j = 0; j < 4; j++) O[nt][j] = 0.f;
    float la = 0.f, lb = 0.f;

    const int ktmax = (q0 + 127) >> 6;
    const int lr = tid >> 3, lc = (tid & 7) * 8;

    auto load_tile = [&](int kt, int stage) {
        const int k0 = kt * 64;
        const uint32_t st = sb + stage * ASTAGE_B;
        #pragma unroll
        for (int i = 0; i < 2; i++) {
            const int r = lr + i * 32;
            const size_t gk = (size_t)(b * NSEQ + k0 + r) * D_IN + h * HDIM + lc;
            const size_t gv = (size_t)(bh * HDIM + r) * NSEQ + k0 + lc;
            const uint32_t so = (uint32_t)(r * KSTR + lc) * 2;
            cp16(st + 0 * TILE_B2 + so, Kh + gk);
            cp16(st + 1 * TILE_B2 + so, Vth + gv);
        }
        asm volatile("cp.async.commit_group;" ::: "memory");
    };

    load_tile(0, 0);

    for (int kt = 0; kt <= ktmax; kt++) {
        if (kt < ktmax) {
            load_tile(kt + 1, (kt + 1) & 1);
            asm volatile("cp.async.wait_group 1;" ::: "memory");
        } else {
            asm volatile("cp.async.wait_group 0;" ::: "memory");
        }
        __syncthreads();

        const int k0 = kt * 64;
        const uint32_t stK = sb + (kt & 1) * ASTAGE_B;
        const uint32_t stV = stK + TILE_B2;

        if (k0 <= q0 + wid * 16 + 15) {
            float S[8][4];
            #pragma unroll
            for (int nt = 0; nt < 8; nt++)
                #pragma unroll
                for (int j = 0; j < 4; j++) S[nt][j] = 0.f;

            #pragma unroll
            for (int ks = 0; ks < 4; ks++) {
                const uint32_t cb = (uint32_t)(ks * 16 + fcol) * 2;
                #pragma unroll
                for (int ntp = 0; ntp < 4; ntp++) {
                    uint32_t bh4[4];
                    ldsm4(bh4, stK + (uint32_t)(ntp * 16 + frow) * (KSTR * 2) + cb);
                    mma_f16(S[ntp * 2 + 0], qh[ks], bh4[0], bh4[2]);
                    mma_f16(S[ntp * 2 + 1], qh[ks], bh4[1], bh4[3]);
                }
            }

            uint32_t ph[4][4];
            #pragma unroll
            for (int nt = 0; nt < 8; nt++) {
                const int c0 = k0 + nt * 8 + tig * 2;
                const int c1 = c0 + 1;
                float p0 = (c0 <= rA) ? fexp2(S[nt][0] * EXP_C) : 0.f;
                float p1 = (c1 <= rA) ? fexp2(S[nt][1] * EXP_C) : 0.f;
                float p2 = (c0 <= rB) ? fexp2(S[nt][2] * EXP_C) : 0.f;
                float p3 = (c1 <= rB) ? fexp2(S[nt][3] * EXP_C) : 0.f;
                la += p0 + p1;
                lb += p2 + p3;
                __half2 h01 = __float22half2_rn(make_float2(p0, p1));
                __half2 h23 = __float22half2_rn(make_float2(p2, p3));
                const int ks = nt >> 1, half = (nt & 1) * 2;
                ph[ks][half + 0] = *(uint32_t*)&h01;
                ph[ks][half + 1] = *(uint32_t*)&h23;
            }

            #pragma unroll
            for (int ks = 0; ks < 4; ks++) {
                const uint32_t cb = (uint32_t)(ks * 16 + fcol) * 2;
                #pragma unroll
                for (int ntp = 0; ntp < 4; ntp++) {
                    uint32_t bh4[4];
                    ldsm4(bh4, stV + (uint32_t)(ntp * 16 + frow) * (KSTR * 2) + cb);
                    mma_f16(O[ntp * 2 + 0], ph[ks], bh4[0], bh4[2]);
                    mma_f16(O[ntp * 2 + 1], ph[ks], bh4[1], bh4[3]);
                }
            }
        }
        __syncthreads();
    }

    la += __shfl_xor_sync(0xFFFFFFFF, la, 1);
    la += __shfl_xor_sync(0xFFFFFFFF, la, 2);
    lb += __shfl_xor_sync(0xFFFFFFFF, lb, 1);
    lb += __shfl_xor_sync(0xFFFFFFFF, lb, 2);
    const float ia = 1.f / la, ib = 1.f / lb;

    #pragma unroll
    for (int nt = 0; nt < 8; nt++) {
        const int col = h * HDIM + nt * 8 + tig * 2;
        __half2 hA = __float22half2_rn(make_float2(O[nt][0] * ia, O[nt][1] * ia));
        __half2 hB = __float22half2_rn(make_float2(O[nt][2] * ib, O[nt][3] * ib));
        *(uint32_t*)(Ch + (size_t)(b * NSEQ + rA) * D_IN + col) = *(uint32_t*)&hA;
        *(uint32_t*)(Ch + (size_t)(b * NSEQ + rB) * D_IN + col) = *(uint32_t*)&hB;
    }
}

// ---------------------------------------------------------------------------
extern "C" void kernel_launch(void* const* d_in, const int* in_sizes, int n_in,
                              void* d_out, int out_size)
{
    const float* X  = (const float*)d_in[0];
    const float* Wq = (const float*)d_in[1];
    const float* Wk = (const float*)d_in[2];
    const float* Wv = (const float*)d_in[3];
    const float* Wo = (const float*)d_in[4];
    const float* bo = (const float*)d_in[5];
    float* out = (float*)d_out;

    __half *pXh, *pCh, *pWth, *pQh, *pKh, *pVth;
    cudaGetSymbolAddress((void**)&pXh, g_Xh);
    cudaGetSymbolAddress((void**)&pCh, g_Ch);
    cudaGetSymbolAddress((void**)&pWth, g_Wth);
    cudaGetSymbolAddress((void**)&pQh, g_Qh);
    cudaGetSymbolAddress((void**)&pKh, g_Kh);
    cudaGetSymbolAddress((void**)&pVth, g_Vth);

    static bool attrs_set = false;
    if (!attrs_set) {
        cudaFuncSetAttribute((const void*)gemm_ld_kernel<0>,
                             cudaFuncAttributeMaxDynamicSharedMemorySize, GSMEM);
        cudaFuncSetAttribute((const void*)gemm_ld_kernel<1>,
                             cudaFuncAttributeMaxDynamicSharedMemorySize, GSMEM);
        cudaFuncSetAttribute(attn_mma_kernel,
                             cudaFuncAttributeMaxDynamicSharedMemorySize, ATTN_SMEM2);
        attrs_set = true;
    }

    const int convBlocks = (MTOT * D_IN) / (256 * 4);

    conv_kernel<<<convBlocks, 256>>>(X, pXh);
    transpose4_kernel<<<dim3(D_IN / 32, D_IN / 32, 4), dim3(32, 8)>>>(
        Wq, Wk, Wv, Wo, pWth);

    gemm_ld_kernel<1><<<dim3(24, MTOT / 128), 256, GSMEM>>>(
        pXh, pWth, nullptr, nullptr, pQh, pKh, pVth);

    attn_mma_kernel<<<dim3(NSEQ / 128, NHEAD, BATCH), 256, ATTN_SMEM2>>>(
        pQh, pKh, pVth, pCh);

    gemm_ld_kernel<0><<<dim3(8, MTOT / 128), 256, GSMEM>>>(
        pCh, pWth + (size_t)3072 * GK, bo, out, nullptr, nullptr, nullptr);
}

// round 16
// speedup vs baseline: 1.0632x; 1.0632x over previous
#include <cuda_runtime.h>
#include <cuda_fp16.h>
#include <cstdint>

// Problem constants
#define D_IN   1024
#define NSEQ   2048
#define BATCH  4
#define NHEAD  16
#define HDIM   64
#define MTOT   (BATCH*NSEQ)   // 8192
#define GK     1024
#define PGRID  304            // persistent grid (2 per SM, 152 SMs)

// ---------------------------------------------------------------------------
// Scratch (no cudaMalloc allowed)
// ---------------------------------------------------------------------------
__device__ __half g_Xh[(size_t)MTOT * D_IN];
__device__ __half g_Ch[(size_t)MTOT * D_IN];            // ctx hi
__device__ __half g_Wth[(size_t)4 * D_IN * D_IN];       // Wq|Wk|Wv|Wo transposed
__device__ __half g_Qh[(size_t)MTOT * D_IN];
__device__ __half g_Kh[(size_t)MTOT * D_IN];
__device__ __half g_Vth[(size_t)BATCH * NHEAD * HDIM * NSEQ];
__device__ int g_ctr[4];                                // work-queue counters

__device__ __forceinline__ float fexp2(float x) {
    float r;
    asm("ex2.approx.f32 %0, %1;" : "=f"(r) : "f"(x));
    return r;
}
__device__ __forceinline__ uint32_t smem_u32(const void* p) {
    uint32_t a;
    asm("{ .reg .u64 t; cvta.to.shared.u64 t, %1; cvt.u32.u64 %0, t; }" : "=r"(a) : "l"(p));
    return a;
}
__device__ __forceinline__ void cp16(uint32_t saddr, const void* gptr) {
    asm volatile("cp.async.cg.shared.global [%0], [%1], 16;" :: "r"(saddr), "l"(gptr));
}
__device__ __forceinline__ void ldsm4(uint32_t* r, uint32_t saddr) {
    asm volatile("ldmatrix.sync.aligned.m8n8.x4.shared.b16 {%0,%1,%2,%3}, [%4];"
        : "=r"(r[0]), "=r"(r[1]), "=r"(r[2]), "=r"(r[3]) : "r"(saddr));
}
__device__ __forceinline__ void mma_f16(float* c, const uint32_t* a,
                                        uint32_t b0, uint32_t b1)
{
    asm volatile(
        "mma.sync.aligned.m16n8k16.row.col.f32.f16.f16.f32 "
        "{%0,%1,%2,%3}, {%4,%5,%6,%7}, {%8,%9}, {%0,%1,%2,%3};"
        : "+f"(c[0]), "+f"(c[1]), "+f"(c[2]), "+f"(c[3])
        : "r"(a[0]), "r"(a[1]), "r"(a[2]), "r"(a[3]), "r"(b0), "r"(b1));
}

// ---------------------------------------------------------------------------
// Convert fp32 -> fp16 (X); block 0 also resets work-queue counters.
// ---------------------------------------------------------------------------
__global__ __launch_bounds__(256) void conv_kernel(
    const float* __restrict__ x, __half* __restrict__ hi)
{
    if (blockIdx.x == 0 && threadIdx.x < 4) g_ctr[threadIdx.x] = 0;
    size_t i = (size_t)blockIdx.x * 256 + threadIdx.x;
    float4 v = ((const float4*)x)[i];
    __half2 hv0 = __float22half2_rn(make_float2(v.x, v.y));
    __half2 hv1 = __float22half2_rn(make_float2(v.z, v.w));
    ((__half2*)hi)[i * 2 + 0] = hv0;
    ((__half2*)hi)[i * 2 + 1] = hv1;
}

// ---------------------------------------------------------------------------
// Batched transpose: z selects Wq/Wk/Wv/Wo -> Wt[z*1024 + N][K] fp16
// ---------------------------------------------------------------------------
__global__ __launch_bounds__(256) void transpose4_kernel(
    const float* __restrict__ W0, const float* __restrict__ W1,
    const float* __restrict__ W2, const float* __restrict__ W3,
    __half* __restrict__ Th)
{
    __shared__ float t[32][33];
    const int z = blockIdx.z;
    const float* W = (z == 0) ? W0 : (z == 1) ? W1 : (z == 2) ? W2 : W3;
    const int rowOff = z * 1024;
    int x0 = blockIdx.x * 32, y0 = blockIdx.y * 32;
    int tx = threadIdx.x, ty = threadIdx.y;  // (32, 8)
    #pragma unroll
    for (int j = 0; j < 32; j += 8)
        t[ty + j][tx] = W[(size_t)(y0 + ty + j) * D_IN + x0 + tx];
    __syncthreads();
    #pragma unroll
    for (int j = 0; j < 32; j += 8)
        Th[(size_t)(rowOff + x0 + ty + j) * GK + y0 + tx] =
            __float2half_rn(t[tx][ty + j]);
}

// ---------------------------------------------------------------------------
// Persistent pipelined fp16 GEMM (1-MMA).
// EPI 0: fp32 + bias (counter 2, 8 cols x 64 rows).
// EPI 1: fused QKV (counter 0, 24 cols x 64 rows, col-fastest).
// ---------------------------------------------------------------------------
#define BK2 32
#define AS2 40
#define MAT_E (128 * AS2)
#define STG_E (4 * MAT_E)
#define GSMEM (2 * STG_E * 2)      // 81920 bytes
#define VT_STR 136

template<int EPI>
__global__ __launch_bounds__(256, 2) void gemm_ld_kernel(
    const __half* __restrict__ Ah_, const __half* __restrict__ Bh_,
    const float* __restrict__ bias, float* __restrict__ C,
    __half* __restrict__ oQh, __half* __restrict__ oKh,
    __half* __restrict__ oVth)
{
    extern __shared__ __half smem[];
    __shared__ int wslot;
    const int tid = threadIdx.x;
    const int wid = tid >> 5, lane = tid & 31;
    const int g = lane >> 2, tig = lane & 3;
    const int warpRow = (wid >> 1) * 32;
    const int warpCol = (wid & 1) * 64;

    const int NCOL = (EPI == 1) ? 24 : 8;
    const int TOTAL = NCOL * (MTOT / 128);
    const int CTR = (EPI == 1) ? 0 : 2;

    const int lr = tid >> 1, lh = tid & 1;
    const uint32_t sbase = smem_u32(smem);
    const uint32_t sb0 = sbase + (lr * AS2 + lh * 16) * 2;
    const int frow = (lane & 7) + ((lane >> 3) & 1) * 8;
    const int fcol = (lane >> 4) * 8;
    const int NIT = GK / BK2;  // 32

    for (;;) {
        if (tid == 0) wslot = atomicAdd(&g_ctr[CTR], 1);
        __syncthreads();
        const int widx = wslot;
        if (widx >= TOTAL) return;
        const int colBase = (widx % NCOL) * 128;
        const int rowBase = (widx / NCOL) * 128;

        const __half* gA0 = Ah_ + (size_t)rowBase * GK;
        const __half* gB0 = Bh_ + (size_t)colBase * GK;
        const size_t gbase = (size_t)lr * GK + lh * 16;

        float acc[2][8][4];
        #pragma unroll
        for (int mt = 0; mt < 2; mt++)
            #pragma unroll
            for (int nt = 0; nt < 8; nt++)
                #pragma unroll
                for (int j = 0; j < 4; j++) acc[mt][nt][j] = 0.f;

        {
            #pragma unroll
            for (int c = 0; c < 2; c++) {
                cp16(sb0 + c * 16 + 0 * MAT_E * 2, gA0 + gbase + c * 8);
                cp16(sb0 + c * 16 + 2 * MAT_E * 2, gB0 + gbase + c * 8);
            }
            asm volatile("cp.async.commit_group;" ::: "memory");
        }

        for (int it = 0; it < NIT; it++) {
            if (it + 1 < NIT) {
                const int k0 = (it + 1) * BK2;
                const uint32_t sb = sb0 + ((it + 1) & 1) * STG_E * 2;
                #pragma unroll
                for (int c = 0; c < 2; c++) {
                    cp16(sb + c * 16 + 0 * MAT_E * 2, gA0 + gbase + k0 + c * 8);
                    cp16(sb + c * 16 + 2 * MAT_E * 2, gB0 + gbase + k0 + c * 8);
                }
                asm volatile("cp.async.commit_group;" ::: "memory");
                asm volatile("cp.async.wait_group 1;" ::: "memory");
            } else {
                asm volatile("cp.async.wait_group 0;" ::: "memory");
            }
            __syncthreads();

            const uint32_t stg = sbase + (it & 1) * STG_E * 2;

            #pragma unroll
            for (int ks = 0; ks < 2; ks++) {
                const uint32_t cb = (uint32_t)(ks * 16 + fcol) * 2;
                uint32_t ah[2][4];
                #pragma unroll
                for (int mt = 0; mt < 2; mt++) {
                    const uint32_t rb = (uint32_t)(warpRow + mt * 16 + frow) * (AS2 * 2);
                    ldsm4(ah[mt], stg + 0 * MAT_E * 2 + rb + cb);
                }
                #pragma unroll
                for (int ntp = 0; ntp < 4; ntp++) {
                    const uint32_t rb = (uint32_t)(warpCol + ntp * 16 + frow) * (AS2 * 2);
                    uint32_t bh4[4];
                    ldsm4(bh4, stg + 2 * MAT_E * 2 + rb + cb);
                    #pragma unroll
                    for (int s = 0; s < 2; s++) {
                        const int nt = ntp * 2 + s;
                        #pragma unroll
                        for (int mt = 0; mt < 2; mt++)
                            mma_f16(acc[mt][nt], ah[mt], bh4[s], bh4[2 + s]);
                    }
                }
            }
            __syncthreads();
        }

        // ---------------- epilogue ----------------
        if (EPI == 1) {
            const int region = colBase >> 10;   // 0:Q 1:K 2:V
            if (region == 2) {
                __half* tH = smem;   // [128][VT_STR]
                #pragma unroll
                for (int mt = 0; mt < 2; mt++) {
                    #pragma unroll
                    for (int nt = 0; nt < 8; nt++) {
                        const int cl = warpCol + nt * 8 + tig * 2;
                        const int rl = warpRow + mt * 16 + g;
                        #pragma unroll
                        for (int j = 0; j < 4; j++) {
                            const int c = cl + (j & 1);
                            const int r = rl + (j >> 1) * 8;
                            tH[c * VT_STR + r] = __float2half_rn(acc[mt][nt][j]);
                        }
                    }
                }
                __syncthreads();
                const int dl = tid >> 1, hf = tid & 1;
                const int bq = rowBase / NSEQ;
                const int seq0 = rowBase & (NSEQ - 1);
                const int h0 = (colBase & 1023) >> 6;
                const size_t orow =
                    ((size_t)(bq * NHEAD + h0) * HDIM + dl) * NSEQ + seq0 + hf * 64;
                const __half* sH = tH + dl * VT_STR + hf * 64;
                #pragma unroll
                for (int u = 0; u < 8; u++)
                    *(uint4*)(oVth + orow + u * 8) = *(const uint4*)(sH + u * 8);
                __syncthreads();
                continue;
            }
            __half* Ho = (region == 0) ? oQh : oKh;
            #pragma unroll
            for (int mt = 0; mt < 2; mt++) {
                #pragma unroll
                for (int nt = 0; nt < 8; nt++) {
                    const int r0 = rowBase + warpRow + mt * 16 + g;
                    const int col = (colBase & 1023) + warpCol + nt * 8 + tig * 2;
                    __half2 h0 = __float22half2_rn(make_float2(acc[mt][nt][0], acc[mt][nt][1]));
                    __half2 h1 = __float22half2_rn(make_float2(acc[mt][nt][2], acc[mt][nt][3]));
                    *(uint32_t*)(Ho + (size_t)r0 * D_IN + col) = *(uint32_t*)&h0;
                    *(uint32_t*)(Ho + (size_t)(r0 + 8) * D_IN + col) = *(uint32_t*)&h1;
                }
            }
            continue;
        }

        #pragma unroll
        for (int mt = 0; mt < 2; mt++) {
            #pragma unroll
            for (int nt = 0; nt < 8; nt++) {
                const int r0 = rowBase + warpRow + mt * 16 + g;
                const int col = colBase + warpCol + nt * 8 + tig * 2;
                float bx = bias[col], by = bias[col + 1];
                float2 v0 = {acc[mt][nt][0] + bx, acc[mt][nt][1] + by};
                float2 v1 = {acc[mt][nt][2] + bx, acc[mt][nt][3] + by};
                *(float2*)(C + (size_t)r0 * D_IN + col) = v0;
                *(float2*)(C + (size_t)(r0 + 8) * D_IN + col) = v1;
            }
        }
    }
}

// ---------------------------------------------------------------------------
// Persistent tensor-core causal flash attention (counter 1, heavy-first).
// ---------------------------------------------------------------------------
#define KSTR 72
#define TILE_B2 (64 * KSTR * 2)
#define ASTAGE_B (2 * TILE_B2)
#define ATTN_SMEM2 (2 * ASTAGE_B)        // 36864 bytes
#define EXP_C 0.1803368801111204f        // log2(e)/8

__global__ __launch_bounds__(256, 2) void attn_mma_kernel(
    const __half* __restrict__ Qh, const __half* __restrict__ Kh,
    const __half* __restrict__ Vth, __half* __restrict__ Ch)
{
    extern __shared__ __half asmem[];
    __shared__ int wslot;
    const uint32_t sb = smem_u32(asmem);

    const int tid = threadIdx.x;
    const int wid = tid >> 5, lane = tid & 31;
    const int g = lane >> 2, tig = lane & 3;
    const int frow = (lane & 7) + ((lane >> 3) & 1) * 8;
    const int fcol = (lane >> 4) * 8;
    const int lr = tid >> 3, lc = (tid & 7) * 8;

    for (;;) {
        if (tid == 0) wslot = atomicAdd(&g_ctr[1], 1);
        __syncthreads();
        const int widx = wslot;
        if (widx >= 1024) return;
        // heavy first: qt = 15 - widx/64 for all 64 bh
        const int q0 = (15 - (widx >> 6)) * 128;
        const int bh = widx & 63;
        const int b = bh >> 4, h = bh & 15;
        const int rA = q0 + wid * 16 + g;
        const int rB = rA + 8;

        const size_t qrow = (size_t)(b * NSEQ + q0 + wid * 16) * D_IN + h * HDIM;
        uint32_t qh[4][4];
        #pragma unroll
        for (int ks = 0; ks < 4; ks++) {
            const int col = ks * 16 + tig * 2;
            qh[ks][0] = *(const uint32_t*)(Qh + qrow + (size_t)g * D_IN + col);
            qh[ks][1] = *(const uint32_t*)(Qh + qrow + (size_t)(g + 8) * D_IN + col);
            qh[ks][2] = *(const uint32_t*)(Qh + qrow + (size_t)g * D_IN + col + 8);
            qh[ks][3] = *(const uint32_t*)(Qh + qrow + (size_t)(g + 8) * D_IN + col + 8);
        }

        float O[8][4];
        #pragma unroll
        for (int nt = 0; nt < 8; nt++)
            #pragma unroll
            for (int j = 0; j < 4; j++) O[nt][j] = 0.f;
        float la = 0.f, lb = 0.f;

        const int ktmax = (q0 + 127) >> 6;

        auto load_tile = [&](int kt, int stage) {
            const int k0 = kt * 64;
            const uint32_t st = sb + stage * ASTAGE_B;
            #pragma unroll
            for (int i = 0; i < 2; i++) {
                const int r = lr + i * 32;
                const size_t gk = (size_t)(b * NSEQ + k0 + r) * D_IN + h * HDIM + lc;
                const size_t gv = (size_t)(bh * HDIM + r) * NSEQ + k0 + lc;
                const uint32_t so = (uint32_t)(r * KSTR + lc) * 2;
                cp16(st + 0 * TILE_B2 + so, Kh + gk);
                cp16(st + 1 * TILE_B2 + so, Vth + gv);
            }
            asm volatile("cp.async.commit_group;" ::: "memory");
        };

        load_tile(0, 0);

        for (int kt = 0; kt <= ktmax; kt++) {
            if (kt < ktmax) {
                load_tile(kt + 1, (kt + 1) & 1);
                asm volatile("cp.async.wait_group 1;" ::: "memory");
            } else {
                asm volatile("cp.async.wait_group 0;" ::: "memory");
            }
            __syncthreads();

            const int k0 = kt * 64;
            const uint32_t stK = sb + (kt & 1) * ASTAGE_B;
            const uint32_t stV = stK + TILE_B2;

            if (k0 <= q0 + wid * 16 + 15) {
                float S[8][4];
                #pragma unroll
                for (int nt = 0; nt < 8; nt++)
                    #pragma unroll
                    for (int j = 0; j < 4; j++) S[nt][j] = 0.f;

                #pragma unroll
                for (int ks = 0; ks < 4; ks++) {
                    const uint32_t cb = (uint32_t)(ks * 16 + fcol) * 2;
                    #pragma unroll
                    for (int ntp = 0; ntp < 4; ntp++) {
                        uint32_t bh4[4];
                        ldsm4(bh4, stK + (uint32_t)(ntp * 16 + frow) * (KSTR * 2) + cb);
                        mma_f16(S[ntp * 2 + 0], qh[ks], bh4[0], bh4[2]);
                        mma_f16(S[ntp * 2 + 1], qh[ks], bh4[1], bh4[3]);
                    }
                }

                uint32_t ph[4][4];
                #pragma unroll
                for (int nt = 0; nt < 8; nt++) {
                    const int c0 = k0 + nt * 8 + tig * 2;
                    const int c1 = c0 + 1;
                    float p0 = (c0 <= rA) ? fexp2(S[nt][0] * EXP_C) : 0.f;
                    float p1 = (c1 <= rA) ? fexp2(S[nt][1] * EXP_C) : 0.f;
                    float p2 = (c0 <= rB) ? fexp2(S[nt][2] * EXP_C) : 0.f;
                    float p3 = (c1 <= rB) ? fexp2(S[nt][3] * EXP_C) : 0.f;
                    la += p0 + p1;
                    lb += p2 + p3;
                    __half2 h01 = __float22half2_rn(make_float2(p0, p1));
                    __half2 h23 = __float22half2_rn(make_float2(p2, p3));
                    const int ks = nt >> 1, half = (nt & 1) * 2;
                    ph[ks][half + 0] = *(uint32_t*)&h01;
                    ph[ks][half + 1] = *(uint32_t*)&h23;
                }

                #pragma unroll
                for (int ks = 0; ks < 4; ks++) {
                    const uint32_t cb = (uint32_t)(ks * 16 + fcol) * 2;
                    #pragma unroll
                    for (int ntp = 0; ntp < 4; ntp++) {
                        uint32_t bh4[4];
                        ldsm4(bh4, stV + (uint32_t)(ntp * 16 + frow) * (KSTR * 2) + cb);
                        mma_f16(O[ntp * 2 + 0], ph[ks], bh4[0], bh4[2]);
                        mma_f16(O[ntp * 2 + 1], ph[ks], bh4[1], bh4[3]);
                    }
                }
            }
            __syncthreads();
        }

        la += __shfl_xor_sync(0xFFFFFFFF, la, 1);
        la += __shfl_xor_sync(0xFFFFFFFF, la, 2);
        lb += __shfl_xor_sync(0xFFFFFFFF, lb, 1);
        lb += __shfl_xor_sync(0xFFFFFFFF, lb, 2);
        const float ia = 1.f / la, ib = 1.f / lb;

        #pragma unroll
        for (int nt = 0; nt < 8; nt++) {
            const int col = h * HDIM + nt * 8 + tig * 2;
            __half2 hA = __float22half2_rn(make_float2(O[nt][0] * ia, O[nt][1] * ia));
            __half2 hB = __float22half2_rn(make_float2(O[nt][2] * ib, O[nt][3] * ib));
            *(uint32_t*)(Ch + (size_t)(b * NSEQ + rA) * D_IN + col) = *(uint32_t*)&hA;
            *(uint32_t*)(Ch + (size_t)(b * NSEQ + rB) * D_IN + col) = *(uint32_t*)&hB;
        }
    }
}

// ---------------------------------------------------------------------------
extern "C" void kernel_launch(void* const* d_in, const int* in_sizes, int n_in,
                              void* d_out, int out_size)
{
    const float* X  = (const float*)d_in[0];
    const float* Wq = (const float*)d_in[1];
    const float* Wk = (const float*)d_in[2];
    const float* Wv = (const float*)d_in[3];
    const float* Wo = (const float*)d_in[4];
    const float* bo = (const float*)d_in[5];
    float* out = (float*)d_out;

    __half *pXh, *pCh, *pWth, *pQh, *pKh, *pVth;
    cudaGetSymbolAddress((void**)&pXh, g_Xh);
    cudaGetSymbolAddress((void**)&pCh, g_Ch);
    cudaGetSymbolAddress((void**)&pWth, g_Wth);
    cudaGetSymbolAddress((void**)&pQh, g_Qh);
    cudaGetSymbolAddress((void**)&pKh, g_Kh);
    cudaGetSymbolAddress((void**)&pVth, g_Vth);

    static bool attrs_set = false;
    if (!attrs_set) {
        cudaFuncSetAttribute((const void*)gemm_ld_kernel<0>,
                             cudaFuncAttributeMaxDynamicSharedMemorySize, GSMEM);
        cudaFuncSetAttribute((const void*)gemm_ld_kernel<1>,
                             cudaFuncAttributeMaxDynamicSharedMemorySize, GSMEM);
        cudaFuncSetAttribute(attn_mma_kernel,
                             cudaFuncAttributeMaxDynamicSharedMemorySize, ATTN_SMEM2);
        attrs_set = true;
    }

    const int convBlocks = (MTOT * D_IN) / (256 * 4);

    conv_kernel<<<convBlocks, 256>>>(X, pXh);   // also resets g_ctr
    transpose4_kernel<<<dim3(D_IN / 32, D_IN / 32, 4), dim3(32, 8)>>>(
        Wq, Wk, Wv, Wo, pWth);

    gemm_ld_kernel<1><<<PGRID, 256, GSMEM>>>(
        pXh, pWth, nullptr, nullptr, pQh, pKh, pVth);

    attn_mma_kernel<<<PGRID, 256, ATTN_SMEM2>>>(pQh, pKh, pVth, pCh);

    gemm_ld_kernel<0><<<PGRID, 256, GSMEM>>>(
        pCh, pWth + (size_t)3072 * GK, bo, out, nullptr, nullptr, nullptr);
}

// round 17
// speedup vs baseline: 1.0733x; 1.0095x over previous
#include <cuda_runtime.h>
#include <cuda_fp16.h>
#include <cstdint>

// Problem constants
#define D_IN   1024
#define NSEQ   2048
#define BATCH  4
#define NHEAD  16
#define HDIM   64
#define MTOT   (BATCH*NSEQ)   // 8192
#define GK     1024
#define PGRID  304            // persistent grid (2 per SM)

// ---------------------------------------------------------------------------
// Scratch (no cudaMalloc allowed)
// ---------------------------------------------------------------------------
__device__ __half g_Xh[(size_t)MTOT * D_IN];
__device__ __half g_Ch[(size_t)MTOT * D_IN];            // ctx hi
__device__ __half g_Wth[(size_t)4 * D_IN * D_IN];       // Wq|Wk|Wv|Wo transposed
__device__ __half g_Qh[(size_t)MTOT * D_IN];
__device__ __half g_Kh[(size_t)MTOT * D_IN];
__device__ __half g_Vth[(size_t)BATCH * NHEAD * HDIM * NSEQ];
__device__ int g_ctr[4];                                // work-queue counters
__device__ int g_ready[64];                             // ctx row-tile arrivals

__device__ __forceinline__ float fexp2(float x) {
    float r;
    asm("ex2.approx.f32 %0, %1;" : "=f"(r) : "f"(x));
    return r;
}
__device__ __forceinline__ uint32_t smem_u32(const void* p) {
    uint32_t a;
    asm("{ .reg .u64 t; cvta.to.shared.u64 t, %1; cvt.u32.u64 %0, t; }" : "=r"(a) : "l"(p));
    return a;
}
__device__ __forceinline__ void cp16(uint32_t saddr, const void* gptr) {
    asm volatile("cp.async.cg.shared.global [%0], [%1], 16;" :: "r"(saddr), "l"(gptr));
}
__device__ __forceinline__ void ldsm4(uint32_t* r, uint32_t saddr) {
    asm volatile("ldmatrix.sync.aligned.m8n8.x4.shared.b16 {%0,%1,%2,%3}, [%4];"
        : "=r"(r[0]), "=r"(r[1]), "=r"(r[2]), "=r"(r[3]) : "r"(saddr));
}
__device__ __forceinline__ void mma_f16(float* c, const uint32_t* a,
                                        uint32_t b0, uint32_t b1)
{
    asm volatile(
        "mma.sync.aligned.m16n8k16.row.col.f32.f16.f16.f32 "
        "{%0,%1,%2,%3}, {%4,%5,%6,%7}, {%8,%9}, {%0,%1,%2,%3};"
        : "+f"(c[0]), "+f"(c[1]), "+f"(c[2]), "+f"(c[3])
        : "r"(a[0]), "r"(a[1]), "r"(a[2]), "r"(a[3]), "r"(b0), "r"(b1));
}

// ---------------------------------------------------------------------------
// Convert fp32 -> fp16 (X); block 0 resets counters + readiness flags.
// ---------------------------------------------------------------------------
__global__ __launch_bounds__(256) void conv_kernel(
    const float* __restrict__ x, __half* __restrict__ hi)
{
    if (blockIdx.x == 0) {
        if (threadIdx.x < 4) g_ctr[threadIdx.x] = 0;
        if (threadIdx.x < 64) g_ready[threadIdx.x] = 0;
    }
    size_t i = (size_t)blockIdx.x * 256 + threadIdx.x;
    float4 v = ((const float4*)x)[i];
    __half2 hv0 = __float22half2_rn(make_float2(v.x, v.y));
    __half2 hv1 = __float22half2_rn(make_float2(v.z, v.w));
    ((__half2*)hi)[i * 2 + 0] = hv0;
    ((__half2*)hi)[i * 2 + 1] = hv1;
}

// ---------------------------------------------------------------------------
// Batched transpose: z selects Wq/Wk/Wv/Wo -> Wt[z*1024 + N][K] fp16
// ---------------------------------------------------------------------------
__global__ __launch_bounds__(256) void transpose4_kernel(
    const float* __restrict__ W0, const float* __restrict__ W1,
    const float* __restrict__ W2, const float* __restrict__ W3,
    __half* __restrict__ Th)
{
    __shared__ float t[32][33];
    const int z = blockIdx.z;
    const float* W = (z == 0) ? W0 : (z == 1) ? W1 : (z == 2) ? W2 : W3;
    const int rowOff = z * 1024;
    int x0 = blockIdx.x * 32, y0 = blockIdx.y * 32;
    int tx = threadIdx.x, ty = threadIdx.y;  // (32, 8)
    #pragma unroll
    for (int j = 0; j < 32; j += 8)
        t[ty + j][tx] = W[(size_t)(y0 + ty + j) * D_IN + x0 + tx];
    __syncthreads();
    #pragma unroll
    for (int j = 0; j < 32; j += 8)
        Th[(size_t)(rowOff + x0 + ty + j) * GK + y0 + tx] =
            __float2half_rn(t[tx][ty + j]);
}

// ---------------------------------------------------------------------------
// Persistent pipelined fp16 QKV GEMM (counter 0, 24 cols x 64 rows).
// ---------------------------------------------------------------------------
#define BK2 32
#define AS2 40
#define MAT_E (128 * AS2)
#define STG_E (4 * MAT_E)
#define GSMEM (2 * STG_E * 2)      // 81920 bytes
#define VT_STR 136

__global__ __launch_bounds__(256, 2) void gemm_qkv_kernel(
    const __half* __restrict__ Ah_, const __half* __restrict__ Bh_,
    __half* __restrict__ oQh, __half* __restrict__ oKh,
    __half* __restrict__ oVth)
{
    extern __shared__ __half smem[];
    __shared__ int wslot;
    const int tid = threadIdx.x;
    const int wid = tid >> 5, lane = tid & 31;
    const int g = lane >> 2, tig = lane & 3;
    const int warpRow = (wid >> 1) * 32;
    const int warpCol = (wid & 1) * 64;

    const int lr = tid >> 1, lh = tid & 1;
    const uint32_t sbase = smem_u32(smem);
    const uint32_t sb0 = sbase + (lr * AS2 + lh * 16) * 2;
    const int frow = (lane & 7) + ((lane >> 3) & 1) * 8;
    const int fcol = (lane >> 4) * 8;
    const int NIT = GK / BK2;  // 32

    for (;;) {
        if (tid == 0) wslot = atomicAdd(&g_ctr[0], 1);
        __syncthreads();
        const int widx = wslot;
        if (widx >= 24 * 64) return;
        const int colBase = (widx % 24) * 128;
        const int rowBase = (widx / 24) * 128;

        const __half* gA0 = Ah_ + (size_t)rowBase * GK;
        const __half* gB0 = Bh_ + (size_t)colBase * GK;
        const size_t gbase = (size_t)lr * GK + lh * 16;

        float acc[2][8][4];
        #pragma unroll
        for (int mt = 0; mt < 2; mt++)
            #pragma unroll
            for (int nt = 0; nt < 8; nt++)
                #pragma unroll
                for (int j = 0; j < 4; j++) acc[mt][nt][j] = 0.f;

        {
            #pragma unroll
            for (int c = 0; c < 2; c++) {
                cp16(sb0 + c * 16 + 0 * MAT_E * 2, gA0 + gbase + c * 8);
                cp16(sb0 + c * 16 + 2 * MAT_E * 2, gB0 + gbase + c * 8);
            }
            asm volatile("cp.async.commit_group;" ::: "memory");
        }

        for (int it = 0; it < NIT; it++) {
            if (it + 1 < NIT) {
                const int k0 = (it + 1) * BK2;
                const uint32_t sb = sb0 + ((it + 1) & 1) * STG_E * 2;
                #pragma unroll
                for (int c = 0; c < 2; c++) {
                    cp16(sb + c * 16 + 0 * MAT_E * 2, gA0 + gbase + k0 + c * 8);
                    cp16(sb + c * 16 + 2 * MAT_E * 2, gB0 + gbase + k0 + c * 8);
                }
                asm volatile("cp.async.commit_group;" ::: "memory");
                asm volatile("cp.async.wait_group 1;" ::: "memory");
            } else {
                asm volatile("cp.async.wait_group 0;" ::: "memory");
            }
            __syncthreads();

            const uint32_t stg = sbase + (it & 1) * STG_E * 2;

            #pragma unroll
            for (int ks = 0; ks < 2; ks++) {
                const uint32_t cb = (uint32_t)(ks * 16 + fcol) * 2;
                uint32_t ah[2][4];
                #pragma unroll
                for (int mt = 0; mt < 2; mt++) {
                    const uint32_t rb = (uint32_t)(warpRow + mt * 16 + frow) * (AS2 * 2);
                    ldsm4(ah[mt], stg + 0 * MAT_E * 2 + rb + cb);
                }
                #pragma unroll
                for (int ntp = 0; ntp < 4; ntp++) {
                    const uint32_t rb = (uint32_t)(warpCol + ntp * 16 + frow) * (AS2 * 2);
                    uint32_t bh4[4];
                    ldsm4(bh4, stg + 2 * MAT_E * 2 + rb + cb);
                    #pragma unroll
                    for (int s = 0; s < 2; s++) {
                        const int nt = ntp * 2 + s;
                        #pragma unroll
                        for (int mt = 0; mt < 2; mt++)
                            mma_f16(acc[mt][nt], ah[mt], bh4[s], bh4[2 + s]);
                    }
                }
            }
            __syncthreads();
        }

        const int region = colBase >> 10;   // 0:Q 1:K 2:V
        if (region == 2) {
            __half* tH = smem;   // [128][VT_STR]
            #pragma unroll
            for (int mt = 0; mt < 2; mt++) {
                #pragma unroll
                for (int nt = 0; nt < 8; nt++) {
                    const int cl = warpCol + nt * 8 + tig * 2;
                    const int rl = warpRow + mt * 16 + g;
                    #pragma unroll
                    for (int j = 0; j < 4; j++) {
                        const int c = cl + (j & 1);
                        const int r = rl + (j >> 1) * 8;
                        tH[c * VT_STR + r] = __float2half_rn(acc[mt][nt][j]);
                    }
                }
            }
            __syncthreads();
            const int dl = tid >> 1, hf = tid & 1;
            const int bq = rowBase / NSEQ;
            const int seq0 = rowBase & (NSEQ - 1);
            const int h0 = (colBase & 1023) >> 6;
            const size_t orow =
                ((size_t)(bq * NHEAD + h0) * HDIM + dl) * NSEQ + seq0 + hf * 64;
            const __half* sH = tH + dl * VT_STR + hf * 64;
            #pragma unroll
            for (int u = 0; u < 8; u++)
                *(uint4*)(oVth + orow + u * 8) = *(const uint4*)(sH + u * 8);
            __syncthreads();
            continue;
        }
        __half* Ho = (region == 0) ? oQh : oKh;
        #pragma unroll
        for (int mt = 0; mt < 2; mt++) {
            #pragma unroll
            for (int nt = 0; nt < 8; nt++) {
                const int r0 = rowBase + warpRow + mt * 16 + g;
                const int col = (colBase & 1023) + warpCol + nt * 8 + tig * 2;
                __half2 h0 = __float22half2_rn(make_float2(acc[mt][nt][0], acc[mt][nt][1]));
                __half2 h1 = __float22half2_rn(make_float2(acc[mt][nt][2], acc[mt][nt][3]));
                *(uint32_t*)(Ho + (size_t)r0 * D_IN + col) = *(uint32_t*)&h0;
                *(uint32_t*)(Ho + (size_t)(r0 + 8) * D_IN + col) = *(uint32_t*)&h1;
            }
        }
    }
}

// ---------------------------------------------------------------------------
// Fused persistent kernel: causal flash attention (counter 1) then
// output projection (counter 2) gated on per-row-tile readiness.
// smem: 40960 B (attn needs 36864, gemm phase 2-slot needs 40960).
// ---------------------------------------------------------------------------
#define KSTR 72
#define TILE_B2 (64 * KSTR * 2)
#define ASTAGE_B (2 * TILE_B2)
#define G2MAT_B (MAT_E * 2)              // 10240 B per matrix slot
#define FUSED_SMEM (4 * G2MAT_B)         // 40960 B (2 stages x 2 slots)
#define EXP_C 0.1803368801111204f        // log2(e)/8

__global__ __launch_bounds__(256, 2) void attn_fused_kernel(
    const __half* __restrict__ Qh, const __half* __restrict__ Kh,
    const __half* __restrict__ Vth, __half* __restrict__ Ch,
    const __half* __restrict__ Wo_, const float* __restrict__ bias,
    float* __restrict__ Out)
{
    extern __shared__ __half asmem[];
    __shared__ int wslot;
    const uint32_t sb = smem_u32(asmem);

    const int tid = threadIdx.x;
    const int wid = tid >> 5, lane = tid & 31;
    const int g = lane >> 2, tig = lane & 3;
    const int frow = (lane & 7) + ((lane >> 3) & 1) * 8;
    const int fcol = (lane >> 4) * 8;

    // ======================= phase 1: attention =======================
    {
        const int lr = tid >> 3, lc = (tid & 7) * 8;
        for (;;) {
            if (tid == 0) wslot = atomicAdd(&g_ctr[1], 1);
            __syncthreads();
            const int widx = wslot;
            if (widx >= 1024) break;
            const int qt = 15 - (widx >> 6);
            const int q0 = qt * 128;
            const int bh = widx & 63;
            const int b = bh >> 4, h = bh & 15;
            const int rA = q0 + wid * 16 + g;
            const int rB = rA + 8;

            const size_t qrow = (size_t)(b * NSEQ + q0 + wid * 16) * D_IN + h * HDIM;
            uint32_t qh[4][4];
            #pragma unroll
            for (int ks = 0; ks < 4; ks++) {
                const int col = ks * 16 + tig * 2;
                qh[ks][0] = *(const uint32_t*)(Qh + qrow + (size_t)g * D_IN + col);
                qh[ks][1] = *(const uint32_t*)(Qh + qrow + (size_t)(g + 8) * D_IN + col);
                qh[ks][2] = *(const uint32_t*)(Qh + qrow + (size_t)g * D_IN + col + 8);
                qh[ks][3] = *(const uint32_t*)(Qh + qrow + (size_t)(g + 8) * D_IN + col + 8);
            }

            float O[8][4];
            #pragma unroll
            for (int nt = 0; nt < 8; nt++)
                #pragma unroll
                for (int j = 0; j < 4; j++) O[nt][j] = 0.f;
            float la = 0.f, lb = 0.f;

            const int ktmax = (q0 + 127) >> 6;

            auto load_tile = [&](int kt, int stage) {
                const int k0 = kt * 64;
                const uint32_t st = sb + stage * ASTAGE_B;
                #pragma unroll
                for (int i = 0; i < 2; i++) {
                    const int r = lr + i * 32;
                    const size_t gk = (size_t)(b * NSEQ + k0 + r) * D_IN + h * HDIM + lc;
                    const size_t gv = (size_t)(bh * HDIM + r) * NSEQ + k0 + lc;
                    const uint32_t so = (uint32_t)(r * KSTR + lc) * 2;
                    cp16(st + 0 * TILE_B2 + so, Kh + gk);
                    cp16(st + 1 * TILE_B2 + so, Vth + gv);
                }
                asm volatile("cp.async.commit_group;" ::: "memory");
            };

            load_tile(0, 0);

            for (int kt = 0; kt <= ktmax; kt++) {
                if (kt < ktmax) {
                    load_tile(kt + 1, (kt + 1) & 1);
                    asm volatile("cp.async.wait_group 1;" ::: "memory");
                } else {
                    asm volatile("cp.async.wait_group 0;" ::: "memory");
                }
                __syncthreads();

                const int k0 = kt * 64;
                const uint32_t stK = sb + (kt & 1) * ASTAGE_B;
                const uint32_t stV = stK + TILE_B2;

                if (k0 <= q0 + wid * 16 + 15) {
                    float S[8][4];
                    #pragma unroll
                    for (int nt = 0; nt < 8; nt++)
                        #pragma unroll
                        for (int j = 0; j < 4; j++) S[nt][j] = 0.f;

                    #pragma unroll
                    for (int ks = 0; ks < 4; ks++) {
                        const uint32_t cb = (uint32_t)(ks * 16 + fcol) * 2;
                        #pragma unroll
                        for (int ntp = 0; ntp < 4; ntp++) {
                            uint32_t bh4[4];
                            ldsm4(bh4, stK + (uint32_t)(ntp * 16 + frow) * (KSTR * 2) + cb);
                            mma_f16(S[ntp * 2 + 0], qh[ks], bh4[0], bh4[2]);
                            mma_f16(S[ntp * 2 + 1], qh[ks], bh4[1], bh4[3]);
                        }
                    }

                    uint32_t ph[4][4];
                    #pragma unroll
                    for (int nt = 0; nt < 8; nt++) {
                        const int c0 = k0 + nt * 8 + tig * 2;
                        const int c1 = c0 + 1;
                        float p0 = (c0 <= rA) ? fexp2(S[nt][0] * EXP_C) : 0.f;
                        float p1 = (c1 <= rA) ? fexp2(S[nt][1] * EXP_C) : 0.f;
                        float p2 = (c0 <= rB) ? fexp2(S[nt][2] * EXP_C) : 0.f;
                        float p3 = (c1 <= rB) ? fexp2(S[nt][3] * EXP_C) : 0.f;
                        la += p0 + p1;
                        lb += p2 + p3;
                        __half2 h01 = __float22half2_rn(make_float2(p0, p1));
                        __half2 h23 = __float22half2_rn(make_float2(p2, p3));
                        const int ks = nt >> 1, half = (nt & 1) * 2;
                        ph[ks][half + 0] = *(uint32_t*)&h01;
                        ph[ks][half + 1] = *(uint32_t*)&h23;
                    }

                    #pragma unroll
                    for (int ks = 0; ks < 4; ks++) {
                        const uint32_t cb = (uint32_t)(ks * 16 + fcol) * 2;
                        #pragma unroll
                        for (int ntp = 0; ntp < 4; ntp++) {
                            uint32_t bh4[4];
                            ldsm4(bh4, stV + (uint32_t)(ntp * 16 + frow) * (KSTR * 2) + cb);
                            mma_f16(O[ntp * 2 + 0], ph[ks], bh4[0], bh4[2]);
                            mma_f16(O[ntp * 2 + 1], ph[ks], bh4[1], bh4[3]);
                        }
                    }
                }
                __syncthreads();
            }

            la += __shfl_xor_sync(0xFFFFFFFF, la, 1);
            la += __shfl_xor_sync(0xFFFFFFFF, la, 2);
            lb += __shfl_xor_sync(0xFFFFFFFF, lb, 1);
            lb += __shfl_xor_sync(0xFFFFFFFF, lb, 2);
            const float ia = 1.f / la, ib = 1.f / lb;

            #pragma unroll
            for (int nt = 0; nt < 8; nt++) {
                const int col = h * HDIM + nt * 8 + tig * 2;
                __half2 hA = __float22half2_rn(make_float2(O[nt][0] * ia, O[nt][1] * ia));
                __half2 hB = __float22half2_rn(make_float2(O[nt][2] * ib, O[nt][3] * ib));
                *(uint32_t*)(Ch + (size_t)(b * NSEQ + rA) * D_IN + col) = *(uint32_t*)&hA;
                *(uint32_t*)(Ch + (size_t)(b * NSEQ + rB) * D_IN + col) = *(uint32_t*)&hB;
            }

            // publish readiness (release)
            __threadfence();
            __syncthreads();
            if (tid == 0) atomicAdd(&g_ready[b * 16 + qt], 1);
        }
    }

    // ===================== phase 2: output projection =====================
    {
        const int warpRow = (wid >> 1) * 32;
        const int warpCol = (wid & 1) * 64;
        const int lr = tid >> 1, lh = tid & 1;
        const uint32_t sb0 = sb + (lr * AS2 + lh * 16) * 2;
        const int NIT = GK / BK2;

        for (;;) {
            if (tid == 0) wslot = atomicAdd(&g_ctr[2], 1);
            __syncthreads();
            const int widx = wslot;
            if (widx >= 512) return;
            // qt descending to match attention completion order
            const int qt = 15 - (widx >> 5);
            const int rem = widx & 31;
            const int b = rem >> 3, colt = rem & 7;
            const int rowBase = (b * 16 + qt) * 128;
            const int colBase = colt * 128;
            const int rt = b * 16 + qt;

            if (tid == 0) {
                while (atomicAdd(&g_ready[rt], 0) < 16) __nanosleep(64);
                wslot = widx;  // keep
            }
            __syncthreads();
            __threadfence();   // acquire before reading Ch

            const __half* gA0 = Ch + (size_t)rowBase * GK;
            const __half* gB0 = Wo_ + (size_t)colBase * GK;
            const size_t gbase = (size_t)lr * GK + lh * 16;

            float acc[2][8][4];
            #pragma unroll
            for (int mt = 0; mt < 2; mt++)
                #pragma unroll
                for (int nt = 0; nt < 8; nt++)
                    #pragma unroll
                    for (int j = 0; j < 4; j++) acc[mt][nt][j] = 0.f;

            {
                #pragma unroll
                for (int c = 0; c < 2; c++) {
                    cp16(sb0 + c * 16 + 0 * G2MAT_B, gA0 + gbase + c * 8);
                    cp16(sb0 + c * 16 + 1 * G2MAT_B, gB0 + gbase + c * 8);
                }
                asm volatile("cp.async.commit_group;" ::: "memory");
            }

            for (int it = 0; it < NIT; it++) {
                if (it + 1 < NIT) {
                    const int k0 = (it + 1) * BK2;
                    const uint32_t sbs = sb0 + ((it + 1) & 1) * 2 * G2MAT_B;
                    #pragma unroll
                    for (int c = 0; c < 2; c++) {
                        cp16(sbs + c * 16 + 0 * G2MAT_B, gA0 + gbase + k0 + c * 8);
                        cp16(sbs + c * 16 + 1 * G2MAT_B, gB0 + gbase + k0 + c * 8);
                    }
                    asm volatile("cp.async.commit_group;" ::: "memory");
                    asm volatile("cp.async.wait_group 1;" ::: "memory");
                } else {
                    asm volatile("cp.async.wait_group 0;" ::: "memory");
                }
                __syncthreads();

                const uint32_t stg = sb + (it & 1) * 2 * G2MAT_B;

                #pragma unroll
                for (int ks = 0; ks < 2; ks++) {
                    const uint32_t cb = (uint32_t)(ks * 16 + fcol) * 2;
                    uint32_t ah[2][4];
                    #pragma unroll
                    for (int mt = 0; mt < 2; mt++) {
                        const uint32_t rb = (uint32_t)(warpRow + mt * 16 + frow) * (AS2 * 2);
                        ldsm4(ah[mt], stg + 0 * G2MAT_B + rb + cb);
                    }
                    #pragma unroll
                    for (int ntp = 0; ntp < 4; ntp++) {
                        const uint32_t rb = (uint32_t)(warpCol + ntp * 16 + frow) * (AS2 * 2);
                        uint32_t bh4[4];
                        ldsm4(bh4, stg + 1 * G2MAT_B + rb + cb);
                        #pragma unroll
                        for (int s = 0; s < 2; s++) {
                            const int nt = ntp * 2 + s;
                            #pragma unroll
                            for (int mt = 0; mt < 2; mt++)
                                mma_f16(acc[mt][nt], ah[mt], bh4[s], bh4[2 + s]);
                        }
                    }
                }
                __syncthreads();
            }

            #pragma unroll
            for (int mt = 0; mt < 2; mt++) {
                #pragma unroll
                for (int nt = 0; nt < 8; nt++) {
                    const int r0 = rowBase + warpRow + mt * 16 + g;
                    const int col = colBase + warpCol + nt * 8 + tig * 2;
                    float bx = bias[col], by = bias[col + 1];
                    float2 v0 = {acc[mt][nt][0] + bx, acc[mt][nt][1] + by};
                    float2 v1 = {acc[mt][nt][2] + bx, acc[mt][nt][3] + by};
                    *(float2*)(Out + (size_t)r0 * D_IN + col) = v0;
                    *(float2*)(Out + (size_t)(r0 + 8) * D_IN + col) = v1;
                }
            }
        }
    }
}

// ---------------------------------------------------------------------------
extern "C" void kernel_launch(void* const* d_in, const int* in_sizes, int n_in,
                              void* d_out, int out_size)
{
    const float* X  = (const float*)d_in[0];
    const float* Wq = (const float*)d_in[1];
    const float* Wk = (const float*)d_in[2];
    const float* Wv = (const float*)d_in[3];
    const float* Wo = (const float*)d_in[4];
    const float* bo = (const float*)d_in[5];
    float* out = (float*)d_out;

    __half *pXh, *pCh, *pWth, *pQh, *pKh, *pVth;
    cudaGetSymbolAddress((void**)&pXh, g_Xh);
    cudaGetSymbolAddress((void**)&pCh, g_Ch);
    cudaGetSymbolAddress((void**)&pWth, g_Wth);
    cudaGetSymbolAddress((void**)&pQh, g_Qh);
    cudaGetSymbolAddress((void**)&pKh, g_Kh);
    cudaGetSymbolAddress((void**)&pVth, g_Vth);

    static bool attrs_set = false;
    if (!attrs_set) {
        cudaFuncSetAttribute(gemm_qkv_kernel,
                             cudaFuncAttributeMaxDynamicSharedMemorySize, GSMEM);
        cudaFuncSetAttribute(attn_fused_kernel,
                             cudaFuncAttributeMaxDynamicSharedMemorySize, FUSED_SMEM);
        attrs_set = true;
    }

    const int convBlocks = (MTOT * D_IN) / (256 * 4);

    conv_kernel<<<convBlocks, 256>>>(X, pXh);   // resets g_ctr + g_ready
    transpose4_kernel<<<dim3(D_IN / 32, D_IN / 32, 4), dim3(32, 8)>>>(
        Wq, Wk, Wv, Wo, pWth);

    gemm_qkv_kernel<<<PGRID, 256, GSMEM>>>(pXh, pWth, pQh, pKh, pVth);

    attn_fused_kernel<<<PGRID, 256, FUSED_SMEM>>>(
        pQh, pKh, pVth, pCh, pWth + (size_t)3072 * GK, bo, out);
}